// round 14
// baseline (speedup 1.0000x reference)
#include <cuda_runtime.h>
#include <cstdint>

#define S_LEN 101
#define BATCH 2048
#define HID 200
#define DIN 120
#define DOUT 12
#define M_TOTAL (S_LEN * BATCH)   // 206848

// Scratch (no allocations allowed -> __device__ globals)
__device__ float g_cur[(size_t)M_TOTAL * HID];        // ~165 MB  cur[b][t][n]

typedef unsigned long long ull;

// ---------- packed f32x2 helpers ----------
__device__ __forceinline__ ull pack2(float lo, float hi) {
    ull r; asm("mov.b64 %0, {%1,%2};" : "=l"(r) : "f"(lo), "f"(hi)); return r;
}
__device__ __forceinline__ void unpack2(ull v, float& lo, float& hi) {
    asm("mov.b64 {%0,%1}, %2;" : "=f"(lo), "=f"(hi) : "l"(v));
}
__device__ __forceinline__ ull add2(ull a, ull b) {
    ull d; asm("add.rn.f32x2 %0, %1, %2;" : "=l"(d) : "l"(a), "l"(b)); return d;
}

// ---------- bf16 / mma / cp.async helpers ----------
__device__ __forceinline__ unsigned bf16x2of(float lo, float hi) {
    unsigned r; asm("cvt.rn.bf16x2.f32 %0, %1, %2;" : "=r"(r) : "f"(hi), "f"(lo));
    return r;   // lo -> bits[0:16), hi -> bits[16:32)
}
__device__ __forceinline__ void bf16_hilo(float x0, float x1, unsigned& h, unsigned& l) {
    h = bf16x2of(x0, x1);
    float h0 = __uint_as_float(h << 16);
    float h1 = __uint_as_float(h & 0xffff0000u);
    l = bf16x2of(x0 - h0, x1 - h1);
}
__device__ __forceinline__ void mma_bf16(float* c,
                                         unsigned a0, unsigned a1, unsigned a2, unsigned a3,
                                         unsigned b0, unsigned b1) {
    asm volatile(
        "mma.sync.aligned.m16n8k16.row.col.f32.bf16.bf16.f32 "
        "{%0,%1,%2,%3}, {%4,%5,%6,%7}, {%8,%9}, {%0,%1,%2,%3};"
        : "+f"(c[0]), "+f"(c[1]), "+f"(c[2]), "+f"(c[3])
        : "r"(a0), "r"(a1), "r"(a2), "r"(a3), "r"(b0), "r"(b1));
}
__device__ __forceinline__ void ldgsts16(unsigned saddr, const void* gptr) {
    asm volatile("cp.async.cg.shared.global [%0], [%1], 16;" :: "r"(saddr), "l"(gptr));
}
#define CPA_COMMIT() asm volatile("cp.async.commit_group;" ::: "memory")
#define CPA_WAIT1()  asm volatile("cp.async.wait_group 1;" ::: "memory")

// ================= Kernel 1: CUR1 = X @ W1 + b1, BF16 3x-split (proven) ======
#define GM_THREADS 256
#define NFMAX 13
#define GM_STR 136
#define GM_STG (128 * GM_STR)
#define BF_BYTES (8 * NFMAX * 32 * 16)                 // 53248
#define GM_SMEM (BF_BYTES + 2 * GM_STG * 4)            // 192512 B
#define MTILES (M_TOTAL / 128)                         // 1616

__global__ __launch_bounds__(GM_THREADS, 1)
void gemm1_mma_kernel(const float* __restrict__ x,
                      const float* __restrict__ W1,
                      const float* __restrict__ b1) {
    extern __shared__ char sm[];
    uint4* Bf  = (uint4*)sm;                           // [8][13][32]
    float* As0 = (float*)(sm + BF_BYTES);              // [128][136]
    float* As1 = As0 + GM_STG;

    const int tid   = threadIdx.x;
    const int warp  = tid >> 5;
    const int lane  = tid & 31;
    const int group = lane >> 2;
    const int tg    = lane & 3;
    const int half  = blockIdx.x & 1;
    const int colbase = half ? 104 : 0;
    const int nfc     = half ? 12 : 13;

    const unsigned sA0 = (unsigned)__cvta_generic_to_shared(As0);
    const unsigned sA1 = (unsigned)__cvta_generic_to_shared(As1);

    auto issue_stage = [&](int mt, unsigned sbase) {
        if (mt < MTILES) {
            const int row0 = mt * 128;
            for (int i = tid; i < 128 * 30; i += GM_THREADS) {
                int r = i / 30, cs = i - r * 30;
                int c = cs / 10, j = cs - c * 10;
                int row = row0 + r;
                int b = row / S_LEN, t = row - b * S_LEN;
                const float* gp = x + ((size_t)((b * 3 + c) * S_LEN + t)) * 40 + j * 4;
                unsigned sp = sbase + (unsigned)((r * GM_STR + c * 40 + j * 4) * 4);
                ldgsts16(sp, gp);
            }
        }
        CPA_COMMIT();
    };

    int m = blockIdx.x >> 1;
    issue_stage(m, sA0);

    for (int i = tid; i < 128 * 8 * 2; i += GM_THREADS) {
        int buf = i >> 10, r = (i >> 3) & 127, w = i & 7;
        (buf ? As1 : As0)[r * GM_STR + 120 + w] = 0.f;
    }

    for (int idx = tid; idx < 8 * nfc * 32; idx += GM_THREADS) {
        int ks  = idx / (nfc * 32);
        int rem = idx - ks * nfc * 32;
        int nf  = rem >> 5;
        int t   = rem & 31;
        int g = t >> 2, q = t & 3;
        int n  = colbase + nf * 8 + g;
        int k0 = ks * 16 + 2 * q;
        int k1 = k0 + 8;
        float w00 = W1[k0 * HID + n];
        float w01 = W1[(k0 + 1) * HID + n];
        float w10 = (k1     < DIN) ? W1[k1 * HID + n]       : 0.f;
        float w11 = (k1 + 1 < DIN) ? W1[(k1 + 1) * HID + n] : 0.f;
        unsigned b0h, b0l, b1h, b1l;
        bf16_hilo(w00, w01, b0h, b0l);
        bf16_hilo(w10, w11, b1h, b1l);
        Bf[(ks * NFMAX + nf) * 32 + t] = make_uint4(b0h, b1h, b0l, b1l);
    }

    float2 bias[NFMAX];
    #pragma unroll
    for (int nf = 0; nf < NFMAX; nf++) {
        if (nf < nfc) {
            int c = colbase + nf * 8 + 2 * tg;
            bias[nf] = make_float2(b1[c], b1[c + 1]);
        } else bias[nf] = make_float2(0.f, 0.f);
    }

    int idx = 0;
    for (; m < MTILES; m += 74, idx ^= 1) {
        issue_stage(m + 74, idx ? sA0 : sA1);
        CPA_WAIT1();
        __syncthreads();

        const float* As = idx ? As1 : As0;
        const float* arow  = As + (warp * 16 + group) * GM_STR;
        const float* arow8 = arow + 8 * GM_STR;

        float acc[NFMAX][4];
        #pragma unroll
        for (int nf = 0; nf < NFMAX; nf++) {
            acc[nf][0] = bias[nf].x; acc[nf][1] = bias[nf].y;
            acc[nf][2] = bias[nf].x; acc[nf][3] = bias[nf].y;
        }

        #pragma unroll
        for (int ks = 0; ks < 8; ks++) {
            const int k0 = ks * 16 + 2 * tg;
            float2 p0 = *(const float2*)(arow  + k0);
            float2 p1 = *(const float2*)(arow8 + k0);
            float2 p2 = *(const float2*)(arow  + k0 + 8);
            float2 p3 = *(const float2*)(arow8 + k0 + 8);
            unsigned ah0, al0, ah1, al1, ah2, al2, ah3, al3;
            bf16_hilo(p0.x, p0.y, ah0, al0);
            bf16_hilo(p1.x, p1.y, ah1, al1);
            bf16_hilo(p2.x, p2.y, ah2, al2);
            bf16_hilo(p3.x, p3.y, ah3, al3);

            const uint4* bp = Bf + ks * NFMAX * 32 + lane;
            #pragma unroll
            for (int p = 0; p < 6; p++) {
                const int n0 = 2 * p, n1 = 2 * p + 1;
                uint4 bA = bp[n0 * 32];                       // LDS.128
                uint4 bB = bp[n1 * 32];
                mma_bf16(acc[n0], ah0, ah1, ah2, ah3, bA.x, bA.y);
                mma_bf16(acc[n1], ah0, ah1, ah2, ah3, bB.x, bB.y);
                mma_bf16(acc[n0], ah0, ah1, ah2, ah3, bA.z, bA.w);
                mma_bf16(acc[n1], ah0, ah1, ah2, ah3, bB.z, bB.w);
                mma_bf16(acc[n0], al0, al1, al2, al3, bA.x, bA.y);
                mma_bf16(acc[n1], al0, al1, al2, al3, bB.x, bB.y);
            }
            if (nfc & 1) {                                    // nf = 12 (even CTAs)
                uint4 b = bp[12 * 32];
                mma_bf16(acc[12], ah0, ah1, ah2, ah3, b.x, b.y);
                mma_bf16(acc[12], ah0, ah1, ah2, ah3, b.z, b.w);
                mma_bf16(acc[12], al0, al1, al2, al3, b.x, b.y);
            }
        }

        const int r0 = m * 128 + warp * 16 + group;
        float* op = g_cur + (size_t)r0 * HID + colbase;
        #pragma unroll
        for (int nf = 0; nf < NFMAX; nf++) {
            if (nf < nfc) {
                *(float2*)(op + nf * 8 + 2 * tg) =
                    make_float2(acc[nf][0], acc[nf][1]);
                *(float2*)(op + 8 * HID + nf * 8 + 2 * tg) =
                    make_float2(acc[nf][2], acc[nf][3]);
            }
        }
        __syncthreads();
    }
}

// ========== Kernel 2: pipelined LIF (2 warps per batch element) ==============
// 14 pairs/CTA (28 warps, 896 threads). Producer warp: LIF1 + scan2 + LIF2,
// publishes mk2 masks to double-buffered smem. Consumer warp (lags 1 t):
// scan3 + LIF3 + count + fused readout. One named barrier per iteration.
// Lane (lane<25) owns neurons 8L..8L+7; W2/W3 bf16 in smem + zero row 200.
#define L_GROUPS 14
#define L_THREADS (L_GROUPS * 64)               // 896
#define LROWS 201
#define LSTRIDE (LROWS * 100)                   // u32 words per layer (20100)
#define LF_SMEM (2 * LSTRIDE * 4)               // 160800 B dynamic

__device__ __forceinline__ float bfLO(unsigned u) { return __uint_as_float(u << 16); }
__device__ __forceinline__ float bfHI(unsigned u) { return __uint_as_float(u & 0xffff0000u); }

// Warp-uniform sparse scan: word m bit j -> neuron 8j+m; 2 spikes per iter
// (2nd slot -> zero row 200, branch-free).
__device__ __forceinline__ void scan8bf(const unsigned* mk, const uint4* Wbase,
                                        int lidx, ull* acc) {
    #pragma unroll
    for (int m = 0; m < 4; m++) {
        ull u = (ull)mk[m] | ((ull)mk[m + 4] << 32);
        while (u) {                                   // uniform across warp
            int p0 = __ffsll(u) - 1;
            u &= u - 1;
            int p1 = __ffsll(u);                      // 0 if empty
            int h0 = ((p0 & 31) << 3) + m + ((p0 >> 5) << 2);
            int q  = p1 - 1;
            int h1 = p1 ? ((q & 31) << 3) + m + ((q >> 5) << 2) : 200;
            u = p1 ? (u & (u - 1)) : 0ull;
            const uint4 w0 = Wbase[h0 * 25 + lidx];
            const uint4 w1 = Wbase[h1 * 25 + lidx];
            acc[0] = add2(acc[0], pack2(bfLO(w0.x), bfHI(w0.x)));
            acc[1] = add2(acc[1], pack2(bfLO(w0.y), bfHI(w0.y)));
            acc[2] = add2(acc[2], pack2(bfLO(w0.z), bfHI(w0.z)));
            acc[3] = add2(acc[3], pack2(bfLO(w0.w), bfHI(w0.w)));
            acc[0] = add2(acc[0], pack2(bfLO(w1.x), bfHI(w1.x)));
            acc[1] = add2(acc[1], pack2(bfLO(w1.y), bfHI(w1.y)));
            acc[2] = add2(acc[2], pack2(bfLO(w1.z), bfHI(w1.z)));
            acc[3] = add2(acc[3], pack2(bfLO(w1.w), bfHI(w1.w)));
        }
    }
}

__global__ __launch_bounds__(L_THREADS, 1)
void lif23_kernel(const float* __restrict__ W2, const float* __restrict__ b2,
                  const float* __restrict__ W3, const float* __restrict__ b3,
                  const float* __restrict__ Wr, const float* __restrict__ br,
                  float* __restrict__ out) {
    extern __shared__ unsigned smw[];                  // [2][201 rows x 100 u32]
    uint4* W2b = (uint4*)smw;                          // row h at +h*25 uint4
    uint4* W3b = (uint4*)(smw + LSTRIDE);
    __shared__ float cnt_sm[L_GROUPS][HID];
    __shared__ __align__(16) unsigned msk[2][L_GROUPS][8];   // mk2 handoff
    const int tid  = threadIdx.x;
    const int pair = tid >> 6;                         // 0..13
    const int role = (tid >> 5) & 1;                   // 0 = producer, 1 = consumer
    const int lane = tid & 31;

    // fp32 -> bf16x2 pack; rows 0..199 = weights, row 200 = zeros
    for (int i = tid; i < HID * HID / 2; i += L_THREADS) {
        float2 a2 = *(const float2*)(W2 + 2 * i);
        float2 a3 = *(const float2*)(W3 + 2 * i);
        smw[i]           = bf16x2of(a2.x, a2.y);
        smw[LSTRIDE + i] = bf16x2of(a3.x, a3.y);
    }
    for (int i = tid; i < 100; i += L_THREADS) {
        smw[HID * HID / 2 + i]           = 0u;         // W2 zero row
        smw[LSTRIDE + HID * HID / 2 + i] = 0u;         // W3 zero row
    }
    __syncthreads();

    const bool iv   = (lane < 25);
    const int  lidx = iv ? lane : 0;
    const int  b    = blockIdx.x * L_GROUPS + pair;
    if (b >= BATCH) return;                            // pair-uniform: both warps skip
    const int  barid = pair + 1;                       // named barriers 1..14

    if (role == 0) {
        // ---------------- producer: LIF1 + scan2 + LIF2 -> msk ----------------
        ull bias2[4] = {0,0,0,0};
        if (iv) {
            #pragma unroll
            for (int q = 0; q < 4; q++) {
                float2 u2 = *(const float2*)(b2 + 8 * lane + 2 * q);
                bias2[q] = pack2(u2.x, u2.y);
            }
        }
        float v1[8], v2[8];
        #pragma unroll
        for (int e = 0; e < 8; e++) { v1[e] = 0.f; v2[e] = 0.f; }
        const float* curb = g_cur + (size_t)b * S_LEN * HID + (iv ? 8 * lane : 0);

        float4 bufA[2], bufB[2];
        #pragma unroll
        for (int q = 0; q < 2; q++) {
            bufA[q] = *(const float4*)(curb + q * HID);
            bufB[q] = *(const float4*)(curb + q * HID + 4);
        }

        for (int k = 0; k <= S_LEN; k++) {
            if (k < S_LEN) {
                float a[8];
                { float4 ca = bufA[k & 1], cb = bufB[k & 1];
                  a[0]=ca.x; a[1]=ca.y; a[2]=ca.z; a[3]=ca.w;
                  a[4]=cb.x; a[5]=cb.y; a[6]=cb.z; a[7]=cb.w; }
                int tp = k + 2; if (tp > S_LEN - 1) tp = S_LEN - 1;
                bufA[k & 1] = *(const float4*)(curb + (size_t)tp * HID);
                bufB[k & 1] = *(const float4*)(curb + (size_t)tp * HID + 4);

                unsigned mk1[8];
                #pragma unroll
                for (int e = 0; e < 8; e++) {
                    v1[e] = 0.5f * (v1[e] + a[e]);
                    bool s = iv && (v1[e] >= 1.0f);
                    if (s) v1[e] = 0.f;
                    mk1[e] = __ballot_sync(0xffffffffu, s);
                }

                ull acc[4] = { bias2[0], bias2[1], bias2[2], bias2[3] };
                scan8bf(mk1, W2b, lidx, acc);
                float c[8];
                unpack2(acc[0], c[0], c[1]); unpack2(acc[1], c[2], c[3]);
                unpack2(acc[2], c[4], c[5]); unpack2(acc[3], c[6], c[7]);

                unsigned mk2[8];
                #pragma unroll
                for (int e = 0; e < 8; e++) {
                    v2[e] = 0.5f * (v2[e] + c[e]);
                    bool s = iv && (v2[e] >= 1.0f);
                    if (s) v2[e] = 0.f;
                    mk2[e] = __ballot_sync(0xffffffffu, s);
                }
                if (lane < 8) msk[k & 1][pair][lane] = mk2[lane];
            }
            asm volatile("bar.sync %0, 64;" :: "r"(barid) : "memory");
        }
    } else {
        // ------------- consumer: scan3 + LIF3 + count + readout (lags 1 t) ----
        ull bias3[4] = {0,0,0,0};
        if (iv) {
            #pragma unroll
            for (int q = 0; q < 4; q++) {
                float2 u3 = *(const float2*)(b3 + 8 * lane + 2 * q);
                bias3[q] = pack2(u3.x, u3.y);
            }
        }
        float v3[8];
        int cnt[8];
        #pragma unroll
        for (int e = 0; e < 8; e++) { v3[e] = 0.f; cnt[e] = 0; }

        for (int k = 0; k <= S_LEN; k++) {
            if (k >= 1) {
                const uint4* mp = (const uint4*)msk[(k - 1) & 1][pair];
                uint4 m0 = mp[0], m1 = mp[1];                  // broadcast LDS
                unsigned mk[8] = { m0.x, m0.y, m0.z, m0.w, m1.x, m1.y, m1.z, m1.w };

                ull acc3[4] = { bias3[0], bias3[1], bias3[2], bias3[3] };
                scan8bf(mk, W3b, lidx, acc3);
                float d[8];
                unpack2(acc3[0], d[0], d[1]); unpack2(acc3[1], d[2], d[3]);
                unpack2(acc3[2], d[4], d[5]); unpack2(acc3[3], d[6], d[7]);

                #pragma unroll
                for (int e = 0; e < 8; e++) {
                    v3[e] = 0.5f * (v3[e] + d[e]);
                    if (v3[e] >= 1.0f) { v3[e] = 0.f; cnt[e]++; }
                }
            }
            asm volatile("bar.sync %0, 64;" :: "r"(barid) : "memory");
        }

        if (iv) {
            *(float4*)&cnt_sm[pair][8 * lane] =
                make_float4((float)cnt[0], (float)cnt[1], (float)cnt[2], (float)cnt[3]);
            *(float4*)&cnt_sm[pair][8 * lane + 4] =
                make_float4((float)cnt[4], (float)cnt[5], (float)cnt[6], (float)cnt[7]);
        }
        __syncwarp();

        float o = -3.0e38f;
        if (lane < DOUT) {
            float acc = 0.f;
            #pragma unroll 4
            for (int kk = 0; kk < HID; kk++)
                acc += cnt_sm[pair][kk] * Wr[kk * DOUT + lane];
            o = acc * (1.0f / 101.0f) + br[lane];
        }
        float mx = o;
        #pragma unroll
        for (int off = 16; off; off >>= 1)
            mx = fmaxf(mx, __shfl_xor_sync(0xffffffffu, mx, off));
        float e = (lane < DOUT) ? expf(o - mx) : 0.f;
        float ssum = e;
        #pragma unroll
        for (int off = 16; off; off >>= 1)
            ssum += __shfl_xor_sync(0xffffffffu, ssum, off);
        if (lane < DOUT) out[b * DOUT + lane] = (o - mx) - logf(ssum);
    }
}

// ================= launch ====================================================
extern "C" void kernel_launch(void* const* d_in, const int* in_sizes, int n_in,
                              void* d_out, int out_size) {
    const float* x  = (const float*)d_in[0];
    const float* W1 = (const float*)d_in[1];
    const float* b1 = (const float*)d_in[2];
    const float* W2 = (const float*)d_in[3];
    const float* b2 = (const float*)d_in[4];
    const float* W3 = (const float*)d_in[5];
    const float* b3 = (const float*)d_in[6];
    const float* Wr = (const float*)d_in[7];
    const float* br = (const float*)d_in[8];
    float* out = (float*)d_out;

    cudaFuncSetAttribute(gemm1_mma_kernel, cudaFuncAttributeMaxDynamicSharedMemorySize, GM_SMEM);
    cudaFuncSetAttribute(lif23_kernel,     cudaFuncAttributeMaxDynamicSharedMemorySize, LF_SMEM);

    const int grid = 148;

    gemm1_mma_kernel<<<grid, GM_THREADS, GM_SMEM>>>(x, W1, b1);
    lif23_kernel   <<<grid, L_THREADS,   LF_SMEM>>>(W2, b2, W3, b3, Wr, br, out);
}

// round 15
// speedup vs baseline: 1.1624x; 1.1624x over previous
#include <cuda_runtime.h>
#include <cstdint>

#define S_LEN 101
#define BATCH 2048
#define HID 200
#define DIN 120
#define DOUT 12
#define M_TOTAL (S_LEN * BATCH)   // 206848

// Scratch (no allocations allowed -> __device__ globals)
__device__ float g_cur[(size_t)M_TOTAL * HID];        // ~165 MB  cur[b][t][n]

typedef unsigned long long ull;

// ---------- packed f32x2 helpers ----------
__device__ __forceinline__ ull pack2(float lo, float hi) {
    ull r; asm("mov.b64 %0, {%1,%2};" : "=l"(r) : "f"(lo), "f"(hi)); return r;
}
__device__ __forceinline__ void unpack2(ull v, float& lo, float& hi) {
    asm("mov.b64 {%0,%1}, %2;" : "=f"(lo), "=f"(hi) : "l"(v));
}
__device__ __forceinline__ ull add2(ull a, ull b) {
    ull d; asm("add.rn.f32x2 %0, %1, %2;" : "=l"(d) : "l"(a), "l"(b)); return d;
}

// ---------- bf16 / mma helpers ----------
__device__ __forceinline__ unsigned bf16x2of(float lo, float hi) {
    unsigned r; asm("cvt.rn.bf16x2.f32 %0, %1, %2;" : "=r"(r) : "f"(hi), "f"(lo));
    return r;   // lo -> bits[0:16), hi -> bits[16:32)
}
__device__ __forceinline__ void bf16_hilo(float x0, float x1, unsigned& h, unsigned& l) {
    h = bf16x2of(x0, x1);
    float h0 = __uint_as_float(h << 16);
    float h1 = __uint_as_float(h & 0xffff0000u);
    l = bf16x2of(x0 - h0, x1 - h1);
}
__device__ __forceinline__ void mma_bf16(float* c,
                                         unsigned a0, unsigned a1, unsigned a2, unsigned a3,
                                         unsigned b0, unsigned b1) {
    asm volatile(
        "mma.sync.aligned.m16n8k16.row.col.f32.bf16.bf16.f32 "
        "{%0,%1,%2,%3}, {%4,%5,%6,%7}, {%8,%9}, {%0,%1,%2,%3};"
        : "+f"(c[0]), "+f"(c[1]), "+f"(c[2]), "+f"(c[3])
        : "r"(a0), "r"(a1), "r"(a2), "r"(a3), "r"(b0), "r"(b1));
}

// ================= Kernel 1: CUR1 = X @ W1 + b1, BF16 3x-split, stage-free ===
// 512 threads / 16 warps; warp = 16-row m-frag of a 256-row tile (808 tiles
// exact). A fragments LDG'd straight from x (each element consumed by exactly
// one thread), converted in registers. No A smem, no barriers in the tile loop.
// Even CTAs: cols 0..103 (13 frags); odd: 104..199 (12). K=120 pad->128.
#define GM_THREADS 512
#define NFMAX 13
#define BF_BYTES (8 * NFMAX * 32 * 16)                 // 53248
#define MTILES2 (M_TOTAL / 256)                        // 808 exact

__global__ __launch_bounds__(GM_THREADS, 1)
void gemm1_mma_kernel(const float* __restrict__ x,
                      const float* __restrict__ W1,
                      const float* __restrict__ b1) {
    extern __shared__ char sm[];
    uint4* Bf = (uint4*)sm;                            // [8][13][32]

    const int tid   = threadIdx.x;
    const int warp  = tid >> 5;                        // 0..15
    const int lane  = tid & 31;
    const int group = lane >> 2;                       // 0..7
    const int tg    = lane & 3;                        // 0..3
    const int half  = blockIdx.x & 1;
    const int colbase = half ? 104 : 0;
    const int nfc     = half ? 12 : 13;

    // ---- build B = W1 half -> fragment-native bf16 hi/lo layout (once) ----
    for (int idx = tid; idx < 8 * nfc * 32; idx += GM_THREADS) {
        int ks  = idx / (nfc * 32);
        int rem = idx - ks * nfc * 32;
        int nf  = rem >> 5;
        int t   = rem & 31;
        int g = t >> 2, q = t & 3;
        int n  = colbase + nf * 8 + g;
        int k0 = ks * 16 + 2 * q;
        int k1 = k0 + 8;
        float w00 = W1[k0 * HID + n];
        float w01 = W1[(k0 + 1) * HID + n];
        float w10 = (k1     < DIN) ? W1[k1 * HID + n]       : 0.f;
        float w11 = (k1 + 1 < DIN) ? W1[(k1 + 1) * HID + n] : 0.f;
        unsigned b0h, b0l, b1h, b1l;
        bf16_hilo(w00, w01, b0h, b0l);
        bf16_hilo(w10, w11, b1h, b1l);
        Bf[(ks * NFMAX + nf) * 32 + t] = make_uint4(b0h, b1h, b0l, b1l);
    }

    float2 bias[NFMAX];
    #pragma unroll
    for (int nf = 0; nf < NFMAX; nf++) {
        if (nf < nfc) {
            int c = colbase + nf * 8 + 2 * tg;
            bias[nf] = make_float2(b1[c], b1[c + 1]);
        } else bias[nf] = make_float2(0.f, 0.f);
    }
    __syncthreads();                                   // Bf visible; no more bars

    for (int mt = blockIdx.x >> 1; mt < MTILES2; mt += 74) {
        const int rowg = mt * 256 + warp * 16 + group; // this thread's row (low)
        const int rowh = rowg + 8;                     // high row
        int bg = rowg / S_LEN, tg0 = rowg - bg * S_LEN;
        int bh = rowh / S_LEN, th0 = rowh - bh * S_LEN;
        const float* r0p = x + (size_t)(bg * 303 + tg0) * 40;  // b*3*101+t rows
        const float* r1p = x + (size_t)(bh * 303 + th0) * 40;

        float acc[NFMAX][4];
        #pragma unroll
        for (int nf = 0; nf < NFMAX; nf++) {
            acc[nf][0] = bias[nf].x; acc[nf][1] = bias[nf].y;
            acc[nf][2] = bias[nf].x; acc[nf][3] = bias[nf].y;
        }

        #pragma unroll
        for (int ks = 0; ks < 8; ks++) {
            const int ka = ks * 16 + 2 * tg;           // 0..118, even
            const int ca = ka / 40, ma = ka - ca * 40;
            float2 p0 = *(const float2*)(r0p + ca * 4040 + ma);
            float2 p1 = *(const float2*)(r1p + ca * 4040 + ma);
            float2 p2, p3;
            if (ks < 7) {
                const int kb = ka + 8;
                const int cb = kb / 40, mb = kb - cb * 40;
                p2 = *(const float2*)(r0p + cb * 4040 + mb);
                p3 = *(const float2*)(r1p + cb * 4040 + mb);
            } else {
                p2 = make_float2(0.f, 0.f);            // k>=120: B rows are zero
                p3 = make_float2(0.f, 0.f);
            }
            unsigned ah0, al0, ah1, al1, ah2, al2, ah3, al3;
            bf16_hilo(p0.x, p0.y, ah0, al0);
            bf16_hilo(p1.x, p1.y, ah1, al1);
            bf16_hilo(p2.x, p2.y, ah2, al2);
            bf16_hilo(p3.x, p3.y, ah3, al3);

            const uint4* bp = Bf + ks * NFMAX * 32 + lane;
            #pragma unroll
            for (int nf = 0; nf < NFMAX; nf++) {
                if (nf < nfc) {
                    uint4 b = bp[nf * 32];                        // LDS.128
                    mma_bf16(acc[nf], ah0, ah1, ah2, ah3, b.x, b.y);   // hi*hi
                    mma_bf16(acc[nf], ah0, ah1, ah2, ah3, b.z, b.w);   // hi*lo
                    mma_bf16(acc[nf], al0, al1, al2, al3, b.x, b.y);   // lo*hi
                }
            }
        }

        float* op = g_cur + (size_t)rowg * HID + colbase;
        #pragma unroll
        for (int nf = 0; nf < NFMAX; nf++) {
            if (nf < nfc) {
                *(float2*)(op + nf * 8 + 2 * tg) =
                    make_float2(acc[nf][0], acc[nf][1]);
                *(float2*)(op + 8 * HID + nf * 8 + 2 * tg) =
                    make_float2(acc[nf][2], acc[nf][3]);
            }
        }
    }
}

// ========== Kernel 2: FUSED LIF1+L2+LIF2+L3+LIF3+readout (R12 best, 103.5us) =
// 14 warps/CTA, warp = batch element. Lane (lane<25) owns neurons 8L..8L+7.
// W2/W3 bf16 in smem + zero row 200. Scan: 8x 32-bit mask loops, 2 spikes per
// iteration (2nd slot -> zero row, branch-free).
#define L_GROUPS 14
#define L_THREADS (L_GROUPS * 32)               // 448
#define LROWS 201
#define LSTRIDE (LROWS * 100)                   // u32 words per layer (20100)
#define LF_SMEM (2 * LSTRIDE * 4)               // 160800 B

__device__ __forceinline__ float bfLO(unsigned u) { return __uint_as_float(u << 16); }
__device__ __forceinline__ float bfHI(unsigned u) { return __uint_as_float(u & 0xffff0000u); }

// Warp-uniform sparse scan, 2 spikes per iteration (2nd slot -> zero row 200).
__device__ __forceinline__ void scan8bf(const unsigned* mk, const uint4* Wbase,
                                        int lidx, ull* acc) {
    #pragma unroll
    for (int m = 0; m < 8; m++) {
        unsigned u = mk[m];
        while (u) {                                   // uniform across warp
            int j0 = __ffs(u) - 1;
            u &= u - 1;
            int j1 = __ffs(u);                        // 0 if empty
            int h0 = 8 * j0 + m;
            int h1 = j1 ? 8 * (j1 - 1) + m : 200;     // 200 = zero row
            u = j1 ? (u & (u - 1)) : 0u;
            const uint4 w0 = Wbase[h0 * 25 + lidx];
            const uint4 w1 = Wbase[h1 * 25 + lidx];
            acc[0] = add2(acc[0], pack2(bfLO(w0.x), bfHI(w0.x)));
            acc[1] = add2(acc[1], pack2(bfLO(w0.y), bfHI(w0.y)));
            acc[2] = add2(acc[2], pack2(bfLO(w0.z), bfHI(w0.z)));
            acc[3] = add2(acc[3], pack2(bfLO(w0.w), bfHI(w0.w)));
            acc[0] = add2(acc[0], pack2(bfLO(w1.x), bfHI(w1.x)));
            acc[1] = add2(acc[1], pack2(bfLO(w1.y), bfHI(w1.y)));
            acc[2] = add2(acc[2], pack2(bfLO(w1.z), bfHI(w1.z)));
            acc[3] = add2(acc[3], pack2(bfLO(w1.w), bfHI(w1.w)));
        }
    }
}

__global__ __launch_bounds__(L_THREADS, 1)
void lif23_kernel(const float* __restrict__ W2, const float* __restrict__ b2,
                  const float* __restrict__ W3, const float* __restrict__ b3,
                  const float* __restrict__ Wr, const float* __restrict__ br,
                  float* __restrict__ out) {
    extern __shared__ unsigned smw[];                  // [2][201 rows x 100 u32]
    uint4* W2b = (uint4*)smw;                          // row h at +h*25 uint4
    uint4* W3b = (uint4*)(smw + LSTRIDE);
    __shared__ float cnt_sm[L_GROUPS][HID];
    const int tid  = threadIdx.x;
    const int grp  = tid >> 5;
    const int lane = tid & 31;

    // fp32 -> bf16x2 pack; rows 0..199 = weights, row 200 = zeros
    for (int i = tid; i < HID * HID / 2; i += L_THREADS) {
        float2 a2 = *(const float2*)(W2 + 2 * i);
        float2 a3 = *(const float2*)(W3 + 2 * i);
        smw[i]           = bf16x2of(a2.x, a2.y);
        smw[LSTRIDE + i] = bf16x2of(a3.x, a3.y);
    }
    for (int i = tid; i < 100; i += L_THREADS) {
        smw[HID * HID / 2 + i]           = 0u;         // W2 zero row
        smw[LSTRIDE + HID * HID / 2 + i] = 0u;         // W3 zero row
    }

    const bool iv   = (lane < 25);
    const int  lidx = iv ? lane : 0;
    ull bias2[4] = {0,0,0,0}, bias3[4] = {0,0,0,0};
    if (iv) {
        #pragma unroll
        for (int q = 0; q < 4; q++) {
            float2 u2 = *(const float2*)(b2 + 8 * lane + 2 * q);
            float2 u3 = *(const float2*)(b3 + 8 * lane + 2 * q);
            bias2[q] = pack2(u2.x, u2.y);
            bias3[q] = pack2(u3.x, u3.y);
        }
    }
    __syncthreads();

    const int b = blockIdx.x * L_GROUPS + grp;
    if (b >= BATCH) return;                            // warp-uniform

    float v1[8], v2[8], v3[8];
    int cnt[8];
    #pragma unroll
    for (int e = 0; e < 8; e++) { v1[e] = 0.f; v2[e] = 0.f; v3[e] = 0.f; cnt[e] = 0; }
    const float* curb = g_cur + (size_t)b * S_LEN * HID + (iv ? 8 * lane : 0);

    float4 bufA[4], bufB[4];
    #pragma unroll
    for (int q = 0; q < 4; q++) {
        bufA[q] = *(const float4*)(curb + q * HID);
        bufB[q] = *(const float4*)(curb + q * HID + 4);
    }

    for (int t = 0; t < S_LEN; t++) {
        float a[8];
        { float4 ca = bufA[t & 3], cb = bufB[t & 3];
          a[0]=ca.x; a[1]=ca.y; a[2]=ca.z; a[3]=ca.w;
          a[4]=cb.x; a[5]=cb.y; a[6]=cb.z; a[7]=cb.w; }
        int tp = t + 4; if (tp > S_LEN - 1) tp = S_LEN - 1;
        bufA[t & 3] = *(const float4*)(curb + (size_t)tp * HID);
        bufB[t & 3] = *(const float4*)(curb + (size_t)tp * HID + 4);

        // ---- LIF1 ----
        unsigned mk1[8];
        #pragma unroll
        for (int e = 0; e < 8; e++) {
            v1[e] = 0.5f * (v1[e] + a[e]);
            bool s = iv && (v1[e] >= 1.0f);
            if (s) v1[e] = 0.f;
            mk1[e] = __ballot_sync(0xffffffffu, s);
        }

        // ---- layer 2: sparse scan + LIF2 ----
        ull acc[4] = { bias2[0], bias2[1], bias2[2], bias2[3] };
        scan8bf(mk1, W2b, lidx, acc);
        float c[8];
        unpack2(acc[0], c[0], c[1]); unpack2(acc[1], c[2], c[3]);
        unpack2(acc[2], c[4], c[5]); unpack2(acc[3], c[6], c[7]);

        unsigned mk2[8];
        #pragma unroll
        for (int e = 0; e < 8; e++) {
            v2[e] = 0.5f * (v2[e] + c[e]);
            bool s = iv && (v2[e] >= 1.0f);
            if (s) v2[e] = 0.f;
            mk2[e] = __ballot_sync(0xffffffffu, s);
        }

        // ---- layer 3: sparse scan + LIF3 ----
        ull acc3[4] = { bias3[0], bias3[1], bias3[2], bias3[3] };
        scan8bf(mk2, W3b, lidx, acc3);
        float d[8];
        unpack2(acc3[0], d[0], d[1]); unpack2(acc3[1], d[2], d[3]);
        unpack2(acc3[2], d[4], d[5]); unpack2(acc3[3], d[6], d[7]);

        #pragma unroll
        for (int e = 0; e < 8; e++) {
            v3[e] = 0.5f * (v3[e] + d[e]);
            if (v3[e] >= 1.0f) { v3[e] = 0.f; cnt[e]++; }
        }
    }

    if (iv) {
        *(float4*)&cnt_sm[grp][8 * lane] =
            make_float4((float)cnt[0], (float)cnt[1], (float)cnt[2], (float)cnt[3]);
        *(float4*)&cnt_sm[grp][8 * lane + 4] =
            make_float4((float)cnt[4], (float)cnt[5], (float)cnt[6], (float)cnt[7]);
    }
    __syncwarp();

    // fused readout + log_softmax
    float o = -3.0e38f;
    if (lane < DOUT) {
        float acc = 0.f;
        #pragma unroll 4
        for (int k = 0; k < HID; k++)
            acc += cnt_sm[grp][k] * Wr[k * DOUT + lane];
        o = acc * (1.0f / 101.0f) + br[lane];
    }
    float mx = o;
    #pragma unroll
    for (int off = 16; off; off >>= 1)
        mx = fmaxf(mx, __shfl_xor_sync(0xffffffffu, mx, off));
    float e = (lane < DOUT) ? expf(o - mx) : 0.f;
    float ssum = e;
    #pragma unroll
    for (int off = 16; off; off >>= 1)
        ssum += __shfl_xor_sync(0xffffffffu, ssum, off);
    if (lane < DOUT) out[b * DOUT + lane] = (o - mx) - logf(ssum);
}

// ================= launch ====================================================
extern "C" void kernel_launch(void* const* d_in, const int* in_sizes, int n_in,
                              void* d_out, int out_size) {
    const float* x  = (const float*)d_in[0];
    const float* W1 = (const float*)d_in[1];
    const float* b1 = (const float*)d_in[2];
    const float* W2 = (const float*)d_in[3];
    const float* b2 = (const float*)d_in[4];
    const float* W3 = (const float*)d_in[5];
    const float* b3 = (const float*)d_in[6];
    const float* Wr = (const float*)d_in[7];
    const float* br = (const float*)d_in[8];
    float* out = (float*)d_out;

    cudaFuncSetAttribute(gemm1_mma_kernel, cudaFuncAttributeMaxDynamicSharedMemorySize, BF_BYTES);
    cudaFuncSetAttribute(lif23_kernel,     cudaFuncAttributeMaxDynamicSharedMemorySize, LF_SMEM);

    const int grid = 148;

    gemm1_mma_kernel<<<grid, GM_THREADS, BF_BYTES>>>(x, W1, b1);
    lif23_kernel   <<<grid, L_THREADS,   LF_SMEM>>>(W2, b2, W3, b3, Wr, br, out);
}